// round 1
// baseline (speedup 1.0000x reference)
#include <cuda_runtime.h>
#include <cstdint>

// Problem constants
static constexpr int E_EDGES = 250000;
static constexpr int NCHUNK  = (E_EDGES + 31) / 32;  // 7813 warp-chunks of 32 edges

#define SQ3f  1.7320508075688772f
#define SQ5f  2.2360679774997896f
#define SQ15f 3.8729833462074170f

typedef unsigned long long u64;

__device__ __forceinline__ u64 pack2(float a, float b) {
    u64 r; asm("mov.b64 %0, {%1, %2};" : "=l"(r) : "f"(a), "f"(b)); return r;
}
__device__ __forceinline__ float2 unpk(u64 v) {
    float2 r; asm("mov.b64 {%0, %1}, %2;" : "=f"(r.x), "=f"(r.y) : "l"(v)); return r;
}
__device__ __forceinline__ void fma2(u64& d, u64 a, u64 b) {
    asm("fma.rn.f32x2 %0, %1, %2, %0;" : "+l"(d) : "l"(a), "l"(b));
}

// Shared memory layout:
//   Wsh:   6144 float2  (48 KB)  layout [i(3)][cpair(32)][d(64)] as f32x2 over (c=2cp, c=2cp+1)
//   stage: 8 warps * 288 float4  (36 KB)  output staging for coalesced stores
static constexpr int W_F2     = 3 * 32 * 64;           // 6144
static constexpr int SMEM_BYTES = W_F2 * 8 + 8 * 288 * 16;  // 49152 + 36864 = 86016

__global__ void __launch_bounds__(256, 2)
sh_embed_kernel(const float* __restrict__ edge_vec,
                const float* __restrict__ inv_g,
                const float* __restrict__ Wg,
                float* __restrict__ out)
{
    extern __shared__ char smem[];
    float2* Wsh       = (float2*)smem;
    float4* stage_all = (float4*)(smem + W_F2 * 8);

    const int tid  = threadIdx.x;
    const int lane = tid & 31;
    const int wid  = tid >> 5;
    float4* stage = stage_all + wid * 288;

    // Cooperative load of W into packed smem layout.
    // t = (i*32 + cp)*64 + d ; W_lin[d, (2cp)*3 + i] and W_lin[d, (2cp+1)*3 + i]
    for (int t = tid; t < W_F2; t += 256) {
        int d  = t & 63;
        int r  = t >> 6;
        int cp = r & 31;
        int i  = r >> 5;
        Wsh[t] = make_float2(Wg[d * 192 + cp * 6 + i],
                             Wg[d * 192 + cp * 6 + 3 + i]);
    }
    __syncthreads();

    const int warpsTotal = gridDim.x * (blockDim.x >> 5);
    #pragma unroll 1
    for (int chunk = blockIdx.x * (blockDim.x >> 5) + wid; chunk < NCHUNK; chunk += warpsTotal) {
        const int eBase = chunk * 32;
        const int e     = eBase + lane;
        const bool valid = (e < E_EDGES);

        // ---- spherical harmonics (lmax=2, component norm), lane = edge ----
        float vx = 1.f, vy = 0.f, vz = 0.f;
        if (valid) {
            vx = edge_vec[e * 3 + 0];
            vy = edge_vec[e * 3 + 1];
            vz = edge_vec[e * 3 + 2];
        }
        float rn = rsqrtf(vx * vx + vy * vy + vz * vz);
        float x = vx * rn, y = vy * rn, z = vz * rn;
        float sh1 = SQ3f * x, sh2 = SQ3f * y, sh3 = SQ3f * z;
        float sh4 = SQ15f * x * z;
        float sh5 = SQ15f * x * y;
        float sh6 = SQ5f * (y * y - 0.5f * (x * x + z * z));
        float sh7 = SQ15f * y * z;
        float sh8 = (0.5f * SQ5f * SQ3f) * (z * z - x * x);

        // ---- per-edge scalar invariants into registers (fully unrolled) ----
        float inv[64];
        if (valid) {
            const float4* p = (const float4*)(inv_g + (size_t)e * 64);
            #pragma unroll
            for (int j = 0; j < 16; j++) {
                float4 q = p[j];
                inv[4*j+0] = q.x; inv[4*j+1] = q.y; inv[4*j+2] = q.z; inv[4*j+3] = q.w;
            }
        } else {
            #pragma unroll
            for (int j = 0; j < 64; j++) inv[j] = 0.f;
        }

        // ---- GEMM (w = inv @ W) fused with SH outer product, 4 channels/iter ----
        #pragma unroll 1
        for (int h = 0; h < 16; h++) {
            const int cpA = 2 * h;
            // uniform (broadcast) shared pointers; cpB stream = +32 ulonglong2
            const ulonglong2* pA0 = (const ulonglong2*)(Wsh + (0 * 32 + cpA) * 64);
            const ulonglong2* pA1 = (const ulonglong2*)(Wsh + (1 * 32 + cpA) * 64);
            const ulonglong2* pA2 = (const ulonglong2*)(Wsh + (2 * 32 + cpA) * 64);

            u64 a0 = 0, a1 = 0, a2 = 0, b0 = 0, b1 = 0, b2 = 0;
            #pragma unroll
            for (int t = 0; t < 32; t++) {          // 2 d per iteration
                u64 ip0 = pack2(inv[2*t],   inv[2*t]);
                u64 ip1 = pack2(inv[2*t+1], inv[2*t+1]);
                ulonglong2 qa0 = pA0[t];
                ulonglong2 qa1 = pA1[t];
                ulonglong2 qa2 = pA2[t];
                ulonglong2 qb0 = pA0[t + 32];
                ulonglong2 qb1 = pA1[t + 32];
                ulonglong2 qb2 = pA2[t + 32];
                fma2(a0, ip0, qa0.x); fma2(a0, ip1, qa0.y);
                fma2(a1, ip0, qa1.x); fma2(a1, ip1, qa1.y);
                fma2(a2, ip0, qa2.x); fma2(a2, ip1, qa2.y);
                fma2(b0, ip0, qb0.x); fma2(b0, ip1, qb0.y);
                fma2(b1, ip0, qb1.x); fma2(b1, ip1, qb1.y);
                fma2(b2, ip0, qb2.x); fma2(b2, ip1, qb2.y);
            }
            float2 wA0 = unpk(a0), wA1 = unpk(a1), wA2 = unpk(a2);
            float2 wB0 = unpk(b0), wB1 = unpk(b1), wB2 = unpk(b2);

            // channels c = 4h .. 4h+3
            float w0s[4] = { wA0.x, wA0.y, wB0.x, wB0.y };
            float w1s[4] = { wA1.x, wA1.y, wB1.x, wB1.y };
            float w2s[4] = { wA2.x, wA2.y, wB2.x, wB2.y };

            float f[36];
            #pragma unroll
            for (int c = 0; c < 4; c++) {
                f[c*9+0] = w0s[c];                 // sh0 = 1, irrep 0
                f[c*9+1] = sh1 * w1s[c];           // irrep 1
                f[c*9+2] = sh2 * w1s[c];
                f[c*9+3] = sh3 * w1s[c];
                f[c*9+4] = sh4 * w2s[c];           // irrep 2
                f[c*9+5] = sh5 * w2s[c];
                f[c*9+6] = sh6 * w2s[c];
                f[c*9+7] = sh7 * w2s[c];
                f[c*9+8] = sh8 * w2s[c];
            }

            // stage: row stride 9 float4 per lane -> (9*lane+s)%8 = (lane+s)%8,
            // conflict-free in both write and read phases
            #pragma unroll
            for (int s = 0; s < 9; s++)
                stage[lane * 9 + s] = make_float4(f[4*s], f[4*s+1], f[4*s+2], f[4*s+3]);
            __syncwarp();

            // coalesced-ish store: 288 float4 = 9 rounds * 32 lanes
            #pragma unroll
            for (int r = 0; r < 9; r++) {
                int idx = r * 32 + lane;
                int ee  = idx / 9;
                int ff  = idx - ee * 9;
                float4 v = stage[idx];
                int eg = eBase + ee;
                if (eg < E_EDGES)
                    ((float4*)out)[(size_t)eg * 144 + h * 9 + ff] = v;
            }
            __syncwarp();
        }
    }
}

extern "C" void kernel_launch(void* const* d_in, const int* in_sizes, int n_in,
                              void* d_out, int out_size) {
    const float* edge_vec = (const float*)d_in[0];   // [E, 3]
    const float* inv      = (const float*)d_in[1];   // [E, 64]
    const float* W        = (const float*)d_in[2];   // [64, 192]
    float* out            = (float*)d_out;           // [E, 64, 9]

    (void)in_sizes; (void)n_in; (void)out_size;

    cudaFuncSetAttribute(sh_embed_kernel,
                         cudaFuncAttributeMaxDynamicSharedMemorySize, SMEM_BYTES);
    // 296 blocks (2/SM target with 84KB smem), 8 warps each -> 2368 warps,
    // grid-stride over 7813 32-edge chunks.
    sh_embed_kernel<<<296, 256, SMEM_BYTES>>>(edge_vec, inv, W, out);
}